// round 6
// baseline (speedup 1.0000x reference)
#include <cuda_runtime.h>
#include <math.h>

#define BB 8
#define CC 64
#define HH 128
#define WW 128
#define OO 64
#define HWSZ (HH*WW)

typedef unsigned long long u64;

__device__ float  g_off [BB*18*HH*WW];
__device__ float  g_mask[BB* 9*HH*WW];
__device__ float2 g_wre2[9*64*64];     // w_dcn transposed+duplicated: [k][c][o] = (w,w)
__device__ float  g_wconv[64*9*28];    // [(c*9+p)][28] : 0..17 off, 18..26 mask, 27 pad

// ---- f32x2 packed helpers -------------------------------------------------
__device__ __forceinline__ u64 pk2(float a, float b) {
    u64 r; asm("mov.b64 %0, {%1,%2};" : "=l"(r) : "f"(a), "f"(b)); return r;
}
__device__ __forceinline__ void fma2(u64& d, u64 a, u64 b) {
    asm("fma.rn.f32x2 %0, %1, %2, %0;" : "+l"(d) : "l"(a), "l"(b));
}
__device__ __forceinline__ u64 add2(u64 a, u64 b) {
    u64 r; asm("add.rn.f32x2 %0, %1, %2;" : "=l"(r) : "l"(a), "l"(b)); return r;
}
__device__ __forceinline__ float2 upk2(u64 v) {
    float2 r; asm("mov.b64 {%0,%1}, %2;" : "=f"(r.x), "=f"(r.y) : "l"(v)); return r;
}

// ---------------------------------------------------------------------------
// prep: weight reorders
// ---------------------------------------------------------------------------
__global__ void prep_kernel(const float* __restrict__ w_dcn,
                            const float* __restrict__ w_off,
                            const float* __restrict__ w_mask) {
    int i = blockIdx.x * 256 + threadIdx.x;
    const int N1 = 9*64*64;
    if (i < N1) {
        int k = i >> 12, c = (i >> 6) & 63, o = i & 63;
        float v = w_dcn[(o*64 + c)*9 + k];
        g_wre2[i] = make_float2(v, v);
    }
    int j = i - N1;
    if (j >= 0 && j < 64*9*28) {
        int cp = j / 28, oc = j % 28;
        int c = cp / 9, p = cp % 9;
        float v = 0.f;
        if (oc < 18)      v = w_off [(oc*64 + c)*9 + p];
        else if (oc < 27) v = w_mask[((oc-18)*64 + c)*9 + p];
        g_wconv[j] = v;
    }
}

// ---------------------------------------------------------------------------
// conv: 3x3, 64 -> 27 ch.  Tile 32x32, 256 thr.
// thread = 8 consecutive px (one row) x 14 oc (7 pairs).  FFMA2 inner.
// ---------------------------------------------------------------------------
__global__ __launch_bounds__(256) void conv_kernel(const float* __restrict__ x,
                                                   const float* __restrict__ b_off,
                                                   const float* __restrict__ b_mask) {
    __shared__ float s_x[8][34][34];
    __shared__ float s_w[72][32];

    const int tid = threadIdx.x;
    const int b  = blockIdx.z;
    const int h0 = blockIdx.y * 32;
    const int x0 = blockIdx.x * 32;

    const int ochalf = tid >> 7;
    const int pos    = tid & 127;
    const int row    = pos >> 2;
    const int col0   = (pos & 3) * 8;
    const int wcolix = ochalf * 16;
    const int ocbase = ochalf * 14;

    u64 acc[7][8];
    #pragma unroll
    for (int a = 0; a < 7; a++)
        #pragma unroll
        for (int j = 0; j < 8; j++) acc[a][j] = 0ull;

    for (int cc = 0; cc < 8; cc++) {
        __syncthreads();
        for (int i = tid; i < 8*34*34; i += 256) {
            int c = i / 1156, rem = i % 1156;
            int r = rem / 34, col = rem % 34;
            int gy = h0 + r - 1, gx = x0 + col - 1;
            float v = 0.f;
            if (gy >= 0 && gy < HH && gx >= 0 && gx < WW)
                v = x[(((b*CC) + cc*8 + c)*HH + gy)*WW + gx];
            s_x[c][r][col] = v;
        }
        for (int i = tid; i < 72*32; i += 256) {
            int r = i >> 5, jj = i & 31;
            float v = 0.f;
            int ocj = (jj < 14) ? jj : (jj >= 16 && jj < 30) ? (jj - 2) : -1;
            if (ocj >= 0) v = g_wconv[(cc*72 + r)*28 + ocj];
            s_w[r][jj] = v;
        }
        __syncthreads();

        #pragma unroll 1
        for (int c = 0; c < 8; c++) {
            #pragma unroll
            for (int di = 0; di < 3; di++) {
                u64 wpk[10];
                #pragma unroll
                for (int j = 0; j < 10; j++) {
                    float t = s_x[c][row + di][col0 + j];
                    wpk[j] = pk2(t, t);
                }
                #pragma unroll
                for (int dj = 0; dj < 3; dj++) {
                    const u64* wp = (const u64*)&s_w[c*9 + di*3 + dj][wcolix];
                    #pragma unroll
                    for (int op = 0; op < 7; op++) {
                        u64 wv = wp[op];
                        #pragma unroll
                        for (int j = 0; j < 8; j++) fma2(acc[op][j], wv, wpk[j + dj]);
                    }
                }
            }
        }
    }

    const int h  = h0 + row;
    const int wc = x0 + col0;
    #pragma unroll
    for (int op = 0; op < 7; op++) {
        float vlo[8], vhi[8];
        #pragma unroll
        for (int j = 0; j < 8; j++) {
            float2 t = upk2(acc[op][j]);
            vlo[j] = t.x; vhi[j] = t.y;
        }
        #pragma unroll
        for (int half = 0; half < 2; half++) {
            int oc = ocbase + 2*op + half;
            if (oc >= 27) continue;
            float* vv = half ? vhi : vlo;
            if (oc < 18) {
                float bb = b_off[oc];
                float* dst = &g_off[((b*18 + oc)*HH + h)*WW + wc];
                *(float4*)&dst[0] = make_float4(vv[0]+bb, vv[1]+bb, vv[2]+bb, vv[3]+bb);
                *(float4*)&dst[4] = make_float4(vv[4]+bb, vv[5]+bb, vv[6]+bb, vv[7]+bb);
            } else {
                float bb = b_mask[oc - 18];
                float* dst = &g_mask[((b*9 + oc - 18)*HH + h)*WW + wc];
                float s[8];
                #pragma unroll
                for (int j = 0; j < 8; j++) s[j] = 1.f / (1.f + expf(-(vv[j]+bb)));
                *(float4*)&dst[0] = make_float4(s[0], s[1], s[2], s[3]);
                *(float4*)&dst[4] = make_float4(s[4], s[5], s[6], s[7]);
            }
        }
    }
}

// ---------------------------------------------------------------------------
// dcn: fused bilinear sample + GEMM.
// Block = (b, row) = 128 px x 64 o.  256 threads, thread tile 8px x 4o.
// Channels in two 32-ch passes. smem 32KB -> occ 2-3 so blocks overlap phases.
// ---------------------------------------------------------------------------
__global__ __launch_bounds__(256) void dcn_kernel(const float* __restrict__ x,
                                                  const float* __restrict__ b_dcn,
                                                  float* __restrict__ out) {
    __shared__ float  s_samp[32*128];   // 16 KB [cl][px]
    __shared__ float2 s_w[32*64];       // 16 KB [cl][o] duplicated pairs

    const int tid = threadIdx.x;
    const int b   = blockIdx.x >> 7;
    const int h   = blockIdx.x & 127;

    // sampling: thread owns pixel sp, 16-channel chunk within each 32-half
    const int sp = tid & 127;
    const int sc = (tid >> 7) * 16;

    // GEMM tile: 8 px x 4 o
    const int p0 = (tid & 15) * 8;
    const int o0 = (tid >> 4) * 4;

    u64 acc[4][4];   // [o][pixel-pair]
    #pragma unroll
    for (int o = 0; o < 4; o++)
        #pragma unroll
        for (int p = 0; p < 4; p++) acc[o][p] = 0ull;

    const float* xb = x + (size_t)b * CC * HWSZ;

    for (int k = 0; k < 9; k++) {
        // per-pixel coords (registers only; reused across both halves)
        float dy = g_off[((b*18 + 2*k    )*HH + h)*WW + sp];
        float dx = g_off[((b*18 + 2*k + 1)*HH + h)*WW + sp];
        float m  = g_mask[((b*9 + k)*HH + h)*WW + sp];
        float py = (float)(h - 1 + k/3) + dy;
        float px = (float)(sp - 1 + k%3) + dx;
        float y0f = floorf(py), x0f = floorf(px);
        float fy = py - y0f, fx = px - x0f;
        int y0 = (int)y0f, xx0 = (int)x0f;
        int y1 = y0 + 1,  xx1 = xx0 + 1;
        float vy0 = (y0  >= 0 && y0  < HH) ? 1.f : 0.f;
        float vy1 = (y1  >= 0 && y1  < HH) ? 1.f : 0.f;
        float vx0 = (xx0 >= 0 && xx0 < WW) ? 1.f : 0.f;
        float vx1 = (xx1 >= 0 && xx1 < WW) ? 1.f : 0.f;
        int y0c = min(max(y0, 0), HH-1), y1c = min(max(y1, 0), HH-1);
        int x0c = min(max(xx0, 0), WW-1), x1c = min(max(xx1, 0), WW-1);
        int a0 = y0c*WW + x0c, a1 = y0c*WW + x1c;
        int a2 = y1c*WW + x0c, a3 = y1c*WW + x1c;
        float q0 = (1.f-fy)*(1.f-fx)*vy0*vx0*m;
        float q1 = (1.f-fy)*fx      *vy0*vx1*m;
        float q2 = fy*(1.f-fx)      *vy1*vx0*m;
        float q3 = fy*fx            *vy1*vx1*m;

        #pragma unroll 1
        for (int half = 0; half < 2; half++) {
            __syncthreads();
            // weight slice [32 c][64 o] as duplicated pairs (coalesced copy)
            const u64* wsrc = (const u64*)&g_wre2[(k*64 + half*32)*64];
            u64* wdst = (u64*)s_w;
            #pragma unroll
            for (int n = 0; n < 8; n++)
                wdst[n*256 + tid] = wsrc[n*256 + tid];
            // sample 16 channels of own pixel
            const float* xh = xb + (size_t)(half*32 + sc) * HWSZ;
            #pragma unroll
            for (int j = 0; j < 16; j++) {
                const float* xc = xh + (size_t)j * HWSZ;
                s_samp[(sc + j)*128 + sp] = q0*xc[a0] + q1*xc[a1] + q2*xc[a2] + q3*xc[a3];
            }
            __syncthreads();
            // GEMM accumulate: acc[o][pp] += w[c][o] * samp[c][pp]
            #pragma unroll 8
            for (int cl = 0; cl < 32; cl++) {
                const ulonglong2* sv = (const ulonglong2*)&s_samp[cl*128 + p0];
                ulonglong2 sA = sv[0];   // pixel pairs (0,1),(2,3)
                ulonglong2 sB = sv[1];   // pixel pairs (4,5),(6,7)
                const ulonglong2* wv = (const ulonglong2*)&s_w[cl*64 + o0];
                ulonglong2 wA = wv[0];   // (o0,o0) (o0+1,o0+1)
                ulonglong2 wB = wv[1];   // (o0+2,..) (o0+3,..)
                fma2(acc[0][0], wA.x, sA.x); fma2(acc[0][1], wA.x, sA.y); fma2(acc[0][2], wA.x, sB.x); fma2(acc[0][3], wA.x, sB.y);
                fma2(acc[1][0], wA.y, sA.x); fma2(acc[1][1], wA.y, sA.y); fma2(acc[1][2], wA.y, sB.x); fma2(acc[1][3], wA.y, sB.y);
                fma2(acc[2][0], wB.x, sA.x); fma2(acc[2][1], wB.x, sA.y); fma2(acc[2][2], wB.x, sB.x); fma2(acc[2][3], wB.x, sB.y);
                fma2(acc[3][0], wB.y, sA.x); fma2(acc[3][1], wB.y, sA.y); fma2(acc[3][2], wB.y, sB.x); fma2(acc[3][3], wB.y, sB.y);
            }
        }
    }

    // epilogue: row h, cols p0..p0+7, outputs o0..o0+3
    #pragma unroll
    for (int o = 0; o < 4; o++) {
        float bb = b_dcn[o0 + o];
        u64 bp = pk2(bb, bb);
        u64 r0 = add2(acc[o][0], bp), r1 = add2(acc[o][1], bp);
        u64 r2 = add2(acc[o][2], bp), r3 = add2(acc[o][3], bp);
        float* dst = &out[((size_t)(b*OO + o0 + o)*HH + h)*WW + p0];
        ulonglong2 v0; v0.x = r0; v0.y = r1;
        ulonglong2 v1; v1.x = r2; v1.y = r3;
        ((ulonglong2*)dst)[0] = v0;
        ((ulonglong2*)dst)[1] = v1;
    }
}

// ---------------------------------------------------------------------------
extern "C" void kernel_launch(void* const* d_in, const int* in_sizes, int n_in,
                              void* d_out, int out_size) {
    const float* x      = (const float*)d_in[0];
    const float* w_off  = (const float*)d_in[1];
    const float* b_off  = (const float*)d_in[2];
    const float* w_mask = (const float*)d_in[3];
    const float* b_mask = (const float*)d_in[4];
    const float* w_dcn  = (const float*)d_in[5];
    const float* b_dcn  = (const float*)d_in[6];
    float* out = (float*)d_out;

    int prep_n = 9*64*64 + 64*9*28;
    prep_kernel<<<(prep_n + 255)/256, 256>>>(w_dcn, w_off, w_mask);
    conv_kernel<<<dim3(WW/32, HH/32, BB), 256>>>(x, b_off, b_mask);
    dcn_kernel<<<BB * HH, 256>>>(x, b_dcn, out);
}